// round 11
// baseline (speedup 1.0000x reference)
#include <cuda_runtime.h>
#include <cuda_fp16.h>
#include <cuda_bf16.h>
#include <math.h>

#define MAXN 100352
#define MAXE 3276800

// ---------------- scratch (__device__ globals) -------------------------------
__device__ int     g_deg[MAXN];
__device__ int     g_rowStart[MAXN];
__device__ int     g_part[1024];
__device__ float   g_dinv[MAXN];
__device__ int     g_csr[MAXE];
__device__ int     g_erank[MAXE];            // per-edge rank within its dst
__device__ int     g_is64;
__device__ int     g_scanctr;
__device__ int     g_scanflag;
__device__ int     g_ctr2;
__device__ __half2 g_hbuf1[(size_t)MAXN * 32];   // X@W1 (prescaled inside k_build)
__device__ __half2 g_hbuf3[(size_t)MAXN * 32];   // h1s = dinv*relu(h1)  (fp16)

__device__ __forceinline__ int load_idx(const void* ei, size_t pos) {
    if (g_is64) return (int)((const long long*)ei)[pos];
    return ((const int*)ei)[pos];
}

// ---------------- fused: zero counters + dtype detect + flag reset -----------
__global__ void k_zero_detect(const int* __restrict__ ei32, int N, int nPairs) {
    int i = blockIdx.x * blockDim.x + threadIdx.x;
    if (i < N) g_deg[i] = 0;
    if (i == 0) { g_scanctr = 0; g_scanflag = 0; g_ctr2 = 0; }
    if (blockIdx.x == 0) {
        __shared__ int sh[256];
        int t = threadIdx.x;
        int acc = 0;
        for (int p = t; p < nPairs; p += 256) acc |= ei32[2 * p + 1];
        sh[t] = acc; __syncthreads();
        for (int off = 128; off > 0; off >>= 1) {
            if (t < off) sh[t] |= sh[t + off];
            __syncthreads();
        }
        if (t == 0) g_is64 = (sh[0] == 0) ? 1 : 0;
    }
}

// ---------------- tensor-core GEMM body (bf16 split, 3-term) -----------------
__device__ __forceinline__ void mma16816(float c[4], unsigned a0, unsigned a1,
                                         unsigned a2, unsigned a3,
                                         unsigned b0, unsigned b1) {
    asm volatile(
        "mma.sync.aligned.m16n8k16.row.col.f32.bf16.bf16.f32 "
        "{%0,%1,%2,%3}, {%4,%5,%6,%7}, {%8,%9}, {%0,%1,%2,%3};"
        : "+f"(c[0]), "+f"(c[1]), "+f"(c[2]), "+f"(c[3])
        : "r"(a0), "r"(a1), "r"(a2), "r"(a3), "r"(b0), "r"(b1));
}

#define KC 32

struct GemmSmem {
    __nv_bfloat16 As_h[128][KC + 2];
    __nv_bfloat16 As_l[128][KC + 2];
    __nv_bfloat16 Wt_h[64][KC + 2];
    __nv_bfloat16 Wt_l[64][KC + 2];
};

__device__ void gemm_body(GemmSmem& s, const float* __restrict__ A,
                          const float* __restrict__ W, __half2* __restrict__ Ch,
                          int M, int K, int blk) {
    int tid  = threadIdx.x;
    int warp = tid >> 5, lane = tid & 31;
    int g    = lane >> 2, tg = lane & 3;
    int m0   = blk * 128;
    int mrow = warp * 16;

    float c[8][4];
#pragma unroll
    for (int t = 0; t < 8; t++)
#pragma unroll
        for (int j = 0; j < 4; j++) c[t][j] = 0.0f;

    int nC = K / KC;
    for (int ch = 0; ch < nC; ch++) {
        int k0 = ch * KC;
#pragma unroll
        for (int i = 0; i < 4; i++) {
            int idx = tid + i * 256;
            int row = idx >> 3, c4 = (idx & 7) * 4;
            float4 v = make_float4(0.f, 0.f, 0.f, 0.f);
            int gr = m0 + row;
            if (gr < M) v = *(const float4*)(A + (size_t)gr * K + k0 + c4);
            float vv[4] = {v.x, v.y, v.z, v.w};
#pragma unroll
            for (int q = 0; q < 4; q++) {
                __nv_bfloat16 hi = __float2bfloat16(vv[q]);
                __nv_bfloat16 lo = __float2bfloat16(vv[q] - __bfloat162float(hi));
                s.As_h[row][c4 + q] = hi;
                s.As_l[row][c4 + q] = lo;
            }
        }
#pragma unroll
        for (int i = 0; i < 8; i++) {
            int idx = tid + i * 256;
            int k = idx >> 6, n = idx & 63;
            float v = W[(size_t)(k0 + k) * 64 + n];
            __nv_bfloat16 hi = __float2bfloat16(v);
            __nv_bfloat16 lo = __float2bfloat16(v - __bfloat162float(hi));
            s.Wt_h[n][k] = hi;
            s.Wt_l[n][k] = lo;
        }
        __syncthreads();

#pragma unroll
        for (int ks = 0; ks < 2; ks++) {
            int kb = ks * 16;
            unsigned ah0 = *(const unsigned*)&s.As_h[mrow + g][kb + tg * 2];
            unsigned ah1 = *(const unsigned*)&s.As_h[mrow + g + 8][kb + tg * 2];
            unsigned ah2 = *(const unsigned*)&s.As_h[mrow + g][kb + tg * 2 + 8];
            unsigned ah3 = *(const unsigned*)&s.As_h[mrow + g + 8][kb + tg * 2 + 8];
            unsigned al0 = *(const unsigned*)&s.As_l[mrow + g][kb + tg * 2];
            unsigned al1 = *(const unsigned*)&s.As_l[mrow + g + 8][kb + tg * 2];
            unsigned al2 = *(const unsigned*)&s.As_l[mrow + g][kb + tg * 2 + 8];
            unsigned al3 = *(const unsigned*)&s.As_l[mrow + g + 8][kb + tg * 2 + 8];
#pragma unroll
            for (int t = 0; t < 8; t++) {
                unsigned bh0 = *(const unsigned*)&s.Wt_h[t * 8 + g][kb + tg * 2];
                unsigned bh1 = *(const unsigned*)&s.Wt_h[t * 8 + g][kb + tg * 2 + 8];
                unsigned bl0 = *(const unsigned*)&s.Wt_l[t * 8 + g][kb + tg * 2];
                unsigned bl1 = *(const unsigned*)&s.Wt_l[t * 8 + g][kb + tg * 2 + 8];
                mma16816(c[t], ah0, ah1, ah2, ah3, bh0, bh1);
                mma16816(c[t], ah0, ah1, ah2, ah3, bl0, bl1);
                mma16816(c[t], al0, al1, al2, al3, bh0, bh1);
            }
        }
        __syncthreads();
    }

    int r0 = m0 + mrow + g;
    int r1 = r0 + 8;
#pragma unroll
    for (int t = 0; t < 8; t++) {
        int col2 = (t * 8 + tg * 2) >> 1;
        if (r0 < M) Ch[(size_t)r0 * 32 + col2] = __floats2half2_rn(c[t][0], c[t][1]);
        if (r1 < M) Ch[(size_t)r1 * 32 + col2] = __floats2half2_rn(c[t][2], c[t][3]);
    }
}

// ---------------- fused: GEMM1 blocks + hist blocks (hist emits edge rank) ---
__global__ void __launch_bounds__(256) k_gemm1_hist(const float* __restrict__ A,
                                                    const float* __restrict__ W,
                                                    int M, int K,
                                                    const void* __restrict__ ei, int E,
                                                    int gemmBlocks) {
    __shared__ GemmSmem s;
    if ((int)blockIdx.x < gemmBlocks) {
        gemm_body(s, A, W, g_hbuf1, M, K, blockIdx.x);
    } else {
        int e = (blockIdx.x - gemmBlocks) * 256 + threadIdx.x;
        if (e < E) {
            int d = load_idx(ei, (size_t)E + e);
            g_erank[e] = atomicAdd(&g_deg[d], 1);
        }
    }
}

// ---------------- k_build: scan + dinv + hbuf1 prescale + scatter ------------
// nb blocks (all resident). Internal barriers via spin flags.
__global__ void __launch_bounds__(256) k_build(const void* __restrict__ ei,
                                               int E, int N, int nb) {
    __shared__ int sh[256];
    __shared__ int shT[256];
    int b = blockIdx.x, t = threadIdx.x, i = b * 256 + t;
    int v = (i < N) ? g_deg[i] : 0;

    // local inclusive scan of degrees
    sh[t] = v; __syncthreads();
    for (int off = 1; off < 256; off <<= 1) {
        int x = (t >= off) ? sh[t - off] : 0;
        __syncthreads();
        sh[t] += x;
        __syncthreads();
    }
    if (t == 255) g_part[b] = sh[255];
    __threadfence();
    __syncthreads();
    if (t == 0) atomicAdd(&g_scanctr, 1);

    if (b == 0) {
        if (t == 0) { while (*(volatile int*)&g_scanctr < nb) {} }
        __syncthreads();
        int t4 = t * 4;
        int a0 = (t4 + 0 < nb) ? g_part[t4 + 0] : 0;
        int a1 = (t4 + 1 < nb) ? g_part[t4 + 1] : 0;
        int a2 = (t4 + 2 < nb) ? g_part[t4 + 2] : 0;
        int a3 = (t4 + 3 < nb) ? g_part[t4 + 3] : 0;
        int s0 = a0, s1 = s0 + a1, s2 = s1 + a2, s3 = s2 + a3;
        shT[t] = s3; __syncthreads();
        for (int off = 1; off < 256; off <<= 1) {
            int x = (t >= off) ? shT[t - off] : 0;
            __syncthreads();
            shT[t] += x;
            __syncthreads();
        }
        int base = shT[t] - s3;
        if (t4 + 0 < nb) g_part[t4 + 0] = base;
        if (t4 + 1 < nb) g_part[t4 + 1] = base + s0;
        if (t4 + 2 < nb) g_part[t4 + 2] = base + s1;
        if (t4 + 3 < nb) g_part[t4 + 3] = base + s2;
        __threadfence();
        __syncthreads();
        if (t == 0) atomicExch(&g_scanflag, 1);
    }
    if (t == 0) { while (*(volatile int*)&g_scanflag == 0) {} }
    __syncthreads();

    // rowStart + dinv for this block's nodes
    float di_local = 0.f;
    if (i < N) {
        g_rowStart[i] = g_part[b] + sh[t] - v;
        di_local = rsqrtf((float)(v + 1));
        g_dinv[i] = di_local;
    }
    __syncthreads();

    // prescale this block's hbuf1 rows (nodes b*256 .. b*256+255)
    {
        int base = b * 256 * 32;          // half2 index of first row
        int limit = (N - b * 256);        // nodes in this block
        if (limit > 256) limit = 256;
        int cnt = limit * 32;
        for (int idx = t; idx < cnt; idx += 256) {
            int ln = idx >> 5;            // local node
            float d = g_dinv[b * 256 + ln];
            float2 vv = __half22float2(g_hbuf1[base + idx]);
            g_hbuf1[base + idx] = __floats2half2_rn(vv.x * d, vv.y * d);
        }
    }

    // all-to-all barrier: every block's rowStart/dinv/scale must be visible
    __threadfence();
    __syncthreads();
    if (t == 0) atomicAdd(&g_ctr2, 1);
    if (t == 0) { while (*(volatile int*)&g_ctr2 < nb) {} }
    __syncthreads();
    __threadfence();

    // grid-stride atomic-free scatter, 4-way batched
    int nthreads = nb * 256;
    int e = b * 256 + t;
    while (e + 3 * nthreads < E) {
        int e0 = e, e1 = e + nthreads, e2 = e + 2 * nthreads, e3 = e + 3 * nthreads;
        int s0 = load_idx(ei, (size_t)e0), d0 = load_idx(ei, (size_t)E + e0);
        int s1 = load_idx(ei, (size_t)e1), d1 = load_idx(ei, (size_t)E + e1);
        int s2 = load_idx(ei, (size_t)e2), d2 = load_idx(ei, (size_t)E + e2);
        int s3 = load_idx(ei, (size_t)e3), d3 = load_idx(ei, (size_t)E + e3);
        int r0 = g_rowStart[d0] + g_erank[e0];
        int r1 = g_rowStart[d1] + g_erank[e1];
        int r2 = g_rowStart[d2] + g_erank[e2];
        int r3 = g_rowStart[d3] + g_erank[e3];
        g_csr[r0] = s0; g_csr[r1] = s1; g_csr[r2] = s2; g_csr[r3] = s3;
        e += 4 * nthreads;
    }
    for (; e < E; e += nthreads) {
        int s = load_idx(ei, (size_t)e);
        int d = load_idx(ei, (size_t)E + e);
        g_csr[g_rowStart[d] + g_erank[e]] = s;
    }
}

// ---------------- agg layer 1: warp per node, prescaled fp16 rows ------------
// h1 = relu(dinv*acc + b1); writes h1s = fp16(dinv*h1) to g_hbuf3.
__global__ void k_agg1(const float* __restrict__ bias, int N) {
    const __half2* hs = (const __half2*)g_hbuf1;

    int gw = (blockIdx.x * blockDim.x + threadIdx.x) >> 5;
    int lane = threadIdx.x & 31;
    if (gw >= N) return;

    int beg = g_rowStart[gw];
    int dg  = g_deg[gw];

    float2 self = __half22float2(hs[(size_t)gw * 32 + lane]);
    float acc0 = self.x, acc1 = self.y;

    int e = beg, end = beg + dg;
    while (e < end) {
        int rem = end - e;
        int idx = 0;
        if (lane < rem) idx = g_csr[e + lane];
        int cnt = rem < 32 ? rem : 32;
        int j = 0;
        for (; j + 8 <= cnt; j += 8) {
            int s0 = __shfl_sync(0xffffffffu, idx, j);
            int s1 = __shfl_sync(0xffffffffu, idx, j + 1);
            int s2 = __shfl_sync(0xffffffffu, idx, j + 2);
            int s3 = __shfl_sync(0xffffffffu, idx, j + 3);
            int s4 = __shfl_sync(0xffffffffu, idx, j + 4);
            int s5 = __shfl_sync(0xffffffffu, idx, j + 5);
            int s6 = __shfl_sync(0xffffffffu, idx, j + 6);
            int s7 = __shfl_sync(0xffffffffu, idx, j + 7);
            float2 v0 = __half22float2(hs[(size_t)s0 * 32 + lane]);
            float2 v1 = __half22float2(hs[(size_t)s1 * 32 + lane]);
            float2 v2 = __half22float2(hs[(size_t)s2 * 32 + lane]);
            float2 v3 = __half22float2(hs[(size_t)s3 * 32 + lane]);
            float2 v4 = __half22float2(hs[(size_t)s4 * 32 + lane]);
            float2 v5 = __half22float2(hs[(size_t)s5 * 32 + lane]);
            float2 v6 = __half22float2(hs[(size_t)s6 * 32 + lane]);
            float2 v7 = __half22float2(hs[(size_t)s7 * 32 + lane]);
            acc0 += ((v0.x + v1.x) + (v2.x + v3.x)) + ((v4.x + v5.x) + (v6.x + v7.x));
            acc1 += ((v0.y + v1.y) + (v2.y + v3.y)) + ((v4.y + v5.y) + (v6.y + v7.y));
        }
        for (; j < cnt; j++) {
            int s = __shfl_sync(0xffffffffu, idx, j);
            float2 v = __half22float2(hs[(size_t)s * 32 + lane]);
            acc0 += v.x;
            acc1 += v.y;
        }
        e += 32;
    }

    float di = g_dinv[gw];
    float2 b = *(const float2*)(bias + 2 * lane);
    float v0 = fmaxf(di * acc0 + b.x, 0.f);
    float v1 = fmaxf(di * acc1 + b.y, 0.f);
    g_hbuf3[(size_t)gw * 32 + lane] = __floats2half2_rn(di * v0, di * v1);
}

// ---------------- agg layer 2 + fused W2 transform ---------------------------
// u[d] = dinv[d] * (sum_{src} h1s[src] + h1s[d]);  out[d] = u[d] @ W2 + b2.
// Grid-stride (fixed grid) so W2 is staged in smem once per block.
__global__ void __launch_bounds__(256) k_agg2w(const float* __restrict__ W2,
                                               const float* __restrict__ b2,
                                               float* __restrict__ out, int N) {
    __shared__ float2 W2s[64][33];   // W2s[k][l] = (W2[k][2l], W2[k][2l+1])
    __shared__ float  b2s[64];

    int t = threadIdx.x;
    for (int idx = t; idx < 2048; idx += 256) {
        int k = idx >> 5, l = idx & 31;
        W2s[k][l] = make_float2(W2[k * 64 + 2 * l], W2[k * 64 + 2 * l + 1]);
    }
    if (t < 64) b2s[t] = b2[t];
    __syncthreads();

    const __half2* hs = (const __half2*)g_hbuf3;
    int warp = t >> 5, lane = t & 31;

    for (int gw = blockIdx.x * 8 + warp; gw < N; gw += gridDim.x * 8) {
        int beg = g_rowStart[gw];
        int dg  = g_deg[gw];

        float2 self = __half22float2(hs[(size_t)gw * 32 + lane]);
        float acc0 = self.x, acc1 = self.y;

        int e = beg, end = beg + dg;
        while (e < end) {
            int rem = end - e;
            int idx = 0;
            if (lane < rem) idx = g_csr[e + lane];
            int cnt = rem < 32 ? rem : 32;
            int j = 0;
            for (; j + 8 <= cnt; j += 8) {
                int s0 = __shfl_sync(0xffffffffu, idx, j);
                int s1 = __shfl_sync(0xffffffffu, idx, j + 1);
                int s2 = __shfl_sync(0xffffffffu, idx, j + 2);
                int s3 = __shfl_sync(0xffffffffu, idx, j + 3);
                int s4 = __shfl_sync(0xffffffffu, idx, j + 4);
                int s5 = __shfl_sync(0xffffffffu, idx, j + 5);
                int s6 = __shfl_sync(0xffffffffu, idx, j + 6);
                int s7 = __shfl_sync(0xffffffffu, idx, j + 7);
                float2 v0 = __half22float2(hs[(size_t)s0 * 32 + lane]);
                float2 v1 = __half22float2(hs[(size_t)s1 * 32 + lane]);
                float2 v2 = __half22float2(hs[(size_t)s2 * 32 + lane]);
                float2 v3 = __half22float2(hs[(size_t)s3 * 32 + lane]);
                float2 v4 = __half22float2(hs[(size_t)s4 * 32 + lane]);
                float2 v5 = __half22float2(hs[(size_t)s5 * 32 + lane]);
                float2 v6 = __half22float2(hs[(size_t)s6 * 32 + lane]);
                float2 v7 = __half22float2(hs[(size_t)s7 * 32 + lane]);
                acc0 += ((v0.x + v1.x) + (v2.x + v3.x)) + ((v4.x + v5.x) + (v6.x + v7.x));
                acc1 += ((v0.y + v1.y) + (v2.y + v3.y)) + ((v4.y + v5.y) + (v6.y + v7.y));
            }
            for (; j < cnt; j++) {
                int s = __shfl_sync(0xffffffffu, idx, j);
                float2 v = __half22float2(hs[(size_t)s * 32 + lane]);
                acc0 += v.x;
                acc1 += v.y;
            }
            e += 32;
        }

        float di = g_dinv[gw];
        float u0 = di * acc0;            // u[2*lane]
        float u1 = di * acc1;            // u[2*lane+1]

        // out row: o[c] = sum_k u[k] * W2[k][c] + b2[c], lane covers c=2l,2l+1
        float o0 = b2s[2 * lane];
        float o1 = b2s[2 * lane + 1];
#pragma unroll
        for (int k2 = 0; k2 < 32; k2++) {
            float a = __shfl_sync(0xffffffffu, u0, k2);   // u[2*k2]
            float bb = __shfl_sync(0xffffffffu, u1, k2);  // u[2*k2+1]
            float2 w0 = W2s[2 * k2][lane];
            float2 w1 = W2s[2 * k2 + 1][lane];
            o0 += a * w0.x + bb * w1.x;
            o1 += a * w0.y + bb * w1.y;
        }
        *(float2*)(out + (size_t)gw * 64 + 2 * lane) = make_float2(o0, o1);
    }
}

// ---------------- launch -----------------------------------------------------
extern "C" void kernel_launch(void* const* d_in, const int* in_sizes, int n_in,
                              void* d_out, int out_size) {
    const float* x  = (const float*)d_in[0];
    const void*  ei = d_in[1];
    const float* W1 = (const float*)d_in[2];
    const float* b1 = (const float*)d_in[3];
    const float* W2 = (const float*)d_in[4];
    const float* b2 = (const float*)d_in[5];
    float* out = (float*)d_out;

    int N = in_sizes[0] / 256;
    int E = in_sizes[1] / 2;

    int nb = (N + 255) / 256;
    int eb = (E + 255) / 256;
    int gemm_blocks = (N + 127) / 128;
    int agg_blocks  = (N + 7) / 8;
    int nPairs = (E < 2048) ? E : 2048;

    k_zero_detect<<<nb, 256>>>((const int*)ei, N, nPairs);               // 1
    k_gemm1_hist<<<gemm_blocks + eb, 256>>>(x, W1, N, 256, ei, E,
                                            gemm_blocks);                // 2
    k_build<<<nb, 256>>>(ei, E, N, nb);                                  // 3
    k_agg1<<<agg_blocks, 256>>>(b1, N);                                  // 4 <- profiled
    k_agg2w<<<2048, 256>>>(W2, b2, out, N);                              // 5
}

// round 13
// speedup vs baseline: 1.2639x; 1.2639x over previous
#include <cuda_runtime.h>
#include <cuda_fp16.h>
#include <cuda_bf16.h>
#include <math.h>

#define MAXN 100352
#define MAXE 3276800

// ---------------- scratch (__device__ globals) -------------------------------
__device__ int     g_deg[MAXN];
__device__ int     g_rowStart[MAXN];
__device__ int     g_part[1024];
__device__ float   g_dinv[MAXN];
__device__ int     g_csr[MAXE];              // BYTE offsets: src * 128
__device__ int     g_erank[MAXE];            // per-edge rank within its dst
__device__ int     g_is64;
__device__ int     g_scanctr;
__device__ int     g_scanflag;
__device__ __half2 g_hbuf1[(size_t)MAXN * 32];   // X@W1 (prescaled after scatter_scale)
__device__ __half2 g_hbuf3[(size_t)MAXN * 32];   // h1s = dinv*relu(h1)  (fp16)
__device__ float   g_buf2[(size_t)MAXN * 64];    // u = agg2 result (fp32)

__device__ __forceinline__ int load_idx(const void* ei, size_t pos) {
    if (g_is64) return (int)((const long long*)ei)[pos];
    return ((const int*)ei)[pos];
}

// ---------------- fused: zero counters + dtype detect + flag reset -----------
__global__ void k_zero_detect(const int* __restrict__ ei32, int N, int nPairs) {
    int i = blockIdx.x * blockDim.x + threadIdx.x;
    if (i < N) g_deg[i] = 0;
    if (i == 0) { g_scanctr = 0; g_scanflag = 0; }
    if (blockIdx.x == 0) {
        __shared__ int sh[256];
        int t = threadIdx.x;
        int acc = 0;
        for (int p = t; p < nPairs; p += 256) acc |= ei32[2 * p + 1];
        sh[t] = acc; __syncthreads();
        for (int off = 128; off > 0; off >>= 1) {
            if (t < off) sh[t] |= sh[t + off];
            __syncthreads();
        }
        if (t == 0) g_is64 = (sh[0] == 0) ? 1 : 0;
    }
}

// ---------------- tensor-core GEMM body (bf16 split, 3-term) -----------------
__device__ __forceinline__ void mma16816(float c[4], unsigned a0, unsigned a1,
                                         unsigned a2, unsigned a3,
                                         unsigned b0, unsigned b1) {
    asm volatile(
        "mma.sync.aligned.m16n8k16.row.col.f32.bf16.bf16.f32 "
        "{%0,%1,%2,%3}, {%4,%5,%6,%7}, {%8,%9}, {%0,%1,%2,%3};"
        : "+f"(c[0]), "+f"(c[1]), "+f"(c[2]), "+f"(c[3])
        : "r"(a0), "r"(a1), "r"(a2), "r"(a3), "r"(b0), "r"(b1));
}

#define KC 32

struct GemmSmem {
    __nv_bfloat16 As_h[128][KC + 2];
    __nv_bfloat16 As_l[128][KC + 2];
    __nv_bfloat16 Wt_h[64][KC + 2];
    __nv_bfloat16 Wt_l[64][KC + 2];
};

// If Cf != nullptr: fp32 epilogue Cf[row*64+col] = c + bias[col].
// Else: fp16 epilogue to Ch (unscaled).
__device__ void gemm_body(GemmSmem& s, const float* __restrict__ A,
                          const float* __restrict__ W, __half2* __restrict__ Ch,
                          float* __restrict__ Cf, const float* __restrict__ bias,
                          int M, int K, int blk) {
    int tid  = threadIdx.x;
    int warp = tid >> 5, lane = tid & 31;
    int g    = lane >> 2, tg = lane & 3;
    int m0   = blk * 128;
    int mrow = warp * 16;

    float c[8][4];
#pragma unroll
    for (int t = 0; t < 8; t++)
#pragma unroll
        for (int j = 0; j < 4; j++) c[t][j] = 0.0f;

    int nC = K / KC;
    for (int ch = 0; ch < nC; ch++) {
        int k0 = ch * KC;
#pragma unroll
        for (int i = 0; i < 4; i++) {
            int idx = tid + i * 256;
            int row = idx >> 3, c4 = (idx & 7) * 4;
            float4 v = make_float4(0.f, 0.f, 0.f, 0.f);
            int gr = m0 + row;
            if (gr < M) v = *(const float4*)(A + (size_t)gr * K + k0 + c4);
            float vv[4] = {v.x, v.y, v.z, v.w};
#pragma unroll
            for (int q = 0; q < 4; q++) {
                __nv_bfloat16 hi = __float2bfloat16(vv[q]);
                __nv_bfloat16 lo = __float2bfloat16(vv[q] - __bfloat162float(hi));
                s.As_h[row][c4 + q] = hi;
                s.As_l[row][c4 + q] = lo;
            }
        }
#pragma unroll
        for (int i = 0; i < 8; i++) {
            int idx = tid + i * 256;
            int k = idx >> 6, n = idx & 63;
            float v = W[(size_t)(k0 + k) * 64 + n];
            __nv_bfloat16 hi = __float2bfloat16(v);
            __nv_bfloat16 lo = __float2bfloat16(v - __bfloat162float(hi));
            s.Wt_h[n][k] = hi;
            s.Wt_l[n][k] = lo;
        }
        __syncthreads();

#pragma unroll
        for (int ks = 0; ks < 2; ks++) {
            int kb = ks * 16;
            unsigned ah0 = *(const unsigned*)&s.As_h[mrow + g][kb + tg * 2];
            unsigned ah1 = *(const unsigned*)&s.As_h[mrow + g + 8][kb + tg * 2];
            unsigned ah2 = *(const unsigned*)&s.As_h[mrow + g][kb + tg * 2 + 8];
            unsigned ah3 = *(const unsigned*)&s.As_h[mrow + g + 8][kb + tg * 2 + 8];
            unsigned al0 = *(const unsigned*)&s.As_l[mrow + g][kb + tg * 2];
            unsigned al1 = *(const unsigned*)&s.As_l[mrow + g + 8][kb + tg * 2];
            unsigned al2 = *(const unsigned*)&s.As_l[mrow + g][kb + tg * 2 + 8];
            unsigned al3 = *(const unsigned*)&s.As_l[mrow + g + 8][kb + tg * 2 + 8];
#pragma unroll
            for (int t = 0; t < 8; t++) {
                unsigned bh0 = *(const unsigned*)&s.Wt_h[t * 8 + g][kb + tg * 2];
                unsigned bh1 = *(const unsigned*)&s.Wt_h[t * 8 + g][kb + tg * 2 + 8];
                unsigned bl0 = *(const unsigned*)&s.Wt_l[t * 8 + g][kb + tg * 2];
                unsigned bl1 = *(const unsigned*)&s.Wt_l[t * 8 + g][kb + tg * 2 + 8];
                mma16816(c[t], ah0, ah1, ah2, ah3, bh0, bh1);
                mma16816(c[t], ah0, ah1, ah2, ah3, bl0, bl1);
                mma16816(c[t], al0, al1, al2, al3, bh0, bh1);
            }
        }
        __syncthreads();
    }

    int r0 = m0 + mrow + g;
    int r1 = r0 + 8;
    if (Cf != nullptr) {
#pragma unroll
        for (int t = 0; t < 8; t++) {
            int col = t * 8 + tg * 2;
            float b0 = bias[col], b1 = bias[col + 1];
            if (r0 < M) {
                Cf[(size_t)r0 * 64 + col]     = c[t][0] + b0;
                Cf[(size_t)r0 * 64 + col + 1] = c[t][1] + b1;
            }
            if (r1 < M) {
                Cf[(size_t)r1 * 64 + col]     = c[t][2] + b0;
                Cf[(size_t)r1 * 64 + col + 1] = c[t][3] + b1;
            }
        }
    } else {
#pragma unroll
        for (int t = 0; t < 8; t++) {
            int col2 = (t * 8 + tg * 2) >> 1;
            if (r0 < M) Ch[(size_t)r0 * 32 + col2] = __floats2half2_rn(c[t][0], c[t][1]);
            if (r1 < M) Ch[(size_t)r1 * 32 + col2] = __floats2half2_rn(c[t][2], c[t][3]);
        }
    }
}

// ---------------- fused: GEMM1 blocks + hist blocks (hist emits edge rank) ---
__global__ void __launch_bounds__(256) k_gemm1_hist(const float* __restrict__ A,
                                                    const float* __restrict__ W,
                                                    int M, int K,
                                                    const void* __restrict__ ei, int E,
                                                    int gemmBlocks) {
    __shared__ GemmSmem s;
    if ((int)blockIdx.x < gemmBlocks) {
        gemm_body(s, A, W, g_hbuf1, nullptr, nullptr, M, K, blockIdx.x);
    } else {
        int e = (blockIdx.x - gemmBlocks) * 256 + threadIdx.x;
        if (e < E) {
            int d = load_idx(ei, (size_t)E + e);
            g_erank[e] = atomicAdd(&g_deg[d], 1);
        }
    }
}

// ---------------- GEMM2: u @ W2 + b2 -> fp32 out -----------------------------
__global__ void __launch_bounds__(256) k_gemm_out(const float* __restrict__ W,
                                                  const float* __restrict__ bias,
                                                  float* __restrict__ out,
                                                  int M, int K) {
    __shared__ GemmSmem s;
    gemm_body(s, (const float*)g_buf2, W, nullptr, out, bias, M, K, blockIdx.x);
}

// ---------------- single-kernel scan (spin-flag, all blocks resident) --------
__global__ void __launch_bounds__(256) k_scanall(int N, int nb) {
    __shared__ int sh[256];
    __shared__ int shT[256];
    int b = blockIdx.x, t = threadIdx.x, i = b * 256 + t;
    int v = (i < N) ? g_deg[i] : 0;

    sh[t] = v; __syncthreads();
    for (int off = 1; off < 256; off <<= 1) {
        int x = (t >= off) ? sh[t - off] : 0;
        __syncthreads();
        sh[t] += x;
        __syncthreads();
    }
    if (t == 255) g_part[b] = sh[255];
    __threadfence();
    __syncthreads();
    if (t == 0) atomicAdd(&g_scanctr, 1);

    if (b == 0) {
        if (t == 0) { while (*(volatile int*)&g_scanctr < nb) {} }
        __syncthreads();
        int t4 = t * 4;
        int a0 = (t4 + 0 < nb) ? g_part[t4 + 0] : 0;
        int a1 = (t4 + 1 < nb) ? g_part[t4 + 1] : 0;
        int a2 = (t4 + 2 < nb) ? g_part[t4 + 2] : 0;
        int a3 = (t4 + 3 < nb) ? g_part[t4 + 3] : 0;
        int s0 = a0, s1 = s0 + a1, s2 = s1 + a2, s3 = s2 + a3;
        shT[t] = s3; __syncthreads();
        for (int off = 1; off < 256; off <<= 1) {
            int x = (t >= off) ? shT[t - off] : 0;
            __syncthreads();
            shT[t] += x;
            __syncthreads();
        }
        int base = shT[t] - s3;
        if (t4 + 0 < nb) g_part[t4 + 0] = base;
        if (t4 + 1 < nb) g_part[t4 + 1] = base + s0;
        if (t4 + 2 < nb) g_part[t4 + 2] = base + s1;
        if (t4 + 3 < nb) g_part[t4 + 3] = base + s2;
        __threadfence();
        __syncthreads();
        if (t == 0) atomicExch(&g_scanflag, 1);
    }

    if (t == 0) { while (*(volatile int*)&g_scanflag == 0) {} }
    __syncthreads();

    if (i < N) {
        g_rowStart[i] = g_part[b] + sh[t] - v;
        g_dinv[i] = rsqrtf((float)(v + 1));
    }
}

// ---------------- fused: atomic-free scatter + prescale-hbuf1 ----------------
// csr entry = src * 128 (byte offset of the fp16 row) so agg avoids the shift.
__global__ void k_scatter_scale(const void* __restrict__ ei, int E, int N,
                                int scatBlocks) {
    if ((int)blockIdx.x < scatBlocks) {
        int e = blockIdx.x * 256 + threadIdx.x;
        if (e < E) {
            int s = load_idx(ei, (size_t)e);
            int d = load_idx(ei, (size_t)E + e);
            g_csr[g_rowStart[d] + g_erank[e]] = s << 7;   // byte offset, no atomic
        }
    } else {
        int idx = (blockIdx.x - scatBlocks) * 256 + threadIdx.x;
        if (idx < N * 32) {
            int row = idx >> 5;
            float2 v = __half22float2(g_hbuf1[idx]);
            float d = g_dinv[row];
            g_hbuf1[idx] = __floats2half2_rn(v.x * d, v.y * d);
        }
    }
}

// ---------------- aggregation: warp per node, HADD2 pair pre-reduction -------
// csr holds byte offsets. Per 8 edges: 8 shfl + 8 LDG + 4 HADD2 + 4 cvt-pairs
// + 8 FADD — about 60% of the previous instruction count (issue-bound kernel).
// mode 0 (layer1): in=g_hbuf1; h1 = relu(dinv*acc + b1); store fp16(dinv*h1)->g_hbuf3.
// mode 1 (layer2): in=g_hbuf3; u = dinv*acc; store fp32 u -> g_buf2.
__global__ void k_agg(const float* __restrict__ bias, int N, int mode) {
    const __half2* hs = (mode == 0) ? (const __half2*)g_hbuf1
                                    : (const __half2*)g_hbuf3;

    int gw = (blockIdx.x * blockDim.x + threadIdx.x) >> 5;
    int lane = threadIdx.x & 31;
    if (gw >= N) return;

    const char* lanep = (const char*)hs + lane * 4;   // this lane's column base
    int beg = g_rowStart[gw];
    int dg  = g_deg[gw];

    float2 self = __half22float2(hs[(size_t)gw * 32 + lane]);
    float acc0 = self.x, acc1 = self.y;

    int e = beg, end = beg + dg;
    while (e < end) {
        int rem = end - e;
        int off = 0;
        if (lane < rem) off = g_csr[e + lane];
        int cnt = rem < 32 ? rem : 32;
        int j = 0;
        for (; j + 8 <= cnt; j += 8) {
            int o0 = __shfl_sync(0xffffffffu, off, j);
            int o1 = __shfl_sync(0xffffffffu, off, j + 1);
            int o2 = __shfl_sync(0xffffffffu, off, j + 2);
            int o3 = __shfl_sync(0xffffffffu, off, j + 3);
            int o4 = __shfl_sync(0xffffffffu, off, j + 4);
            int o5 = __shfl_sync(0xffffffffu, off, j + 5);
            int o6 = __shfl_sync(0xffffffffu, off, j + 6);
            int o7 = __shfl_sync(0xffffffffu, off, j + 7);
            __half2 v0 = *(const __half2*)(lanep + o0);
            __half2 v1 = *(const __half2*)(lanep + o1);
            __half2 v2 = *(const __half2*)(lanep + o2);
            __half2 v3 = *(const __half2*)(lanep + o3);
            __half2 v4 = *(const __half2*)(lanep + o4);
            __half2 v5 = *(const __half2*)(lanep + o5);
            __half2 v6 = *(const __half2*)(lanep + o6);
            __half2 v7 = *(const __half2*)(lanep + o7);
            float2 f01 = __half22float2(__hadd2(v0, v1));
            float2 f23 = __half22float2(__hadd2(v2, v3));
            float2 f45 = __half22float2(__hadd2(v4, v5));
            float2 f67 = __half22float2(__hadd2(v6, v7));
            acc0 += (f01.x + f23.x) + (f45.x + f67.x);
            acc1 += (f01.y + f23.y) + (f45.y + f67.y);
        }
        if (j + 4 <= cnt) {
            int o0 = __shfl_sync(0xffffffffu, off, j);
            int o1 = __shfl_sync(0xffffffffu, off, j + 1);
            int o2 = __shfl_sync(0xffffffffu, off, j + 2);
            int o3 = __shfl_sync(0xffffffffu, off, j + 3);
            __half2 v0 = *(const __half2*)(lanep + o0);
            __half2 v1 = *(const __half2*)(lanep + o1);
            __half2 v2 = *(const __half2*)(lanep + o2);
            __half2 v3 = *(const __half2*)(lanep + o3);
            float2 f01 = __half22float2(__hadd2(v0, v1));
            float2 f23 = __half22float2(__hadd2(v2, v3));
            acc0 += f01.x + f23.x;
            acc1 += f01.y + f23.y;
            j += 4;
        }
        for (; j < cnt; j++) {
            int o = __shfl_sync(0xffffffffu, off, j);
            float2 f = __half22float2(*(const __half2*)(lanep + o));
            acc0 += f.x;
            acc1 += f.y;
        }
        e += 32;
    }

    float di = g_dinv[gw];
    if (mode == 0) {
        float2 b = *(const float2*)(bias + 2 * lane);
        float v0 = fmaxf(di * acc0 + b.x, 0.f);
        float v1 = fmaxf(di * acc1 + b.y, 0.f);
        g_hbuf3[(size_t)gw * 32 + lane] = __floats2half2_rn(di * v0, di * v1);
    } else {
        *(float2*)((float*)g_buf2 + (size_t)gw * 64 + 2 * lane) =
            make_float2(di * acc0, di * acc1);
    }
}

// ---------------- launch -----------------------------------------------------
extern "C" void kernel_launch(void* const* d_in, const int* in_sizes, int n_in,
                              void* d_out, int out_size) {
    const float* x  = (const float*)d_in[0];
    const void*  ei = d_in[1];
    const float* W1 = (const float*)d_in[2];
    const float* b1 = (const float*)d_in[3];
    const float* W2 = (const float*)d_in[4];
    const float* b2 = (const float*)d_in[5];
    float* out = (float*)d_out;

    int N = in_sizes[0] / 256;
    int E = in_sizes[1] / 2;

    int nb = (N + 255) / 256;
    int eb = (E + 255) / 256;
    int gemm_blocks  = (N + 127) / 128;
    int agg_blocks   = (N + 7) / 8;
    int scale_blocks = (N * 32 + 255) / 256;
    int nPairs = (E < 2048) ? E : 2048;

    k_zero_detect<<<nb, 256>>>((const int*)ei, N, nPairs);               // 1
    k_gemm1_hist<<<gemm_blocks + eb, 256>>>(x, W1, N, 256, ei, E,
                                            gemm_blocks);                // 2
    k_scanall<<<nb, 256>>>(N, nb);                                       // 3
    k_scatter_scale<<<eb + scale_blocks, 256>>>(ei, E, N, eb);           // 4 <- profiled
    k_agg<<<agg_blocks, 256>>>(b1, N, 0);                                // 5
    k_agg<<<agg_blocks, 256>>>(b2, N, 1);                                // 6
    k_gemm_out<<<gemm_blocks, 256>>>(W2, b2, out, N, 64);                // 7
}